// round 14
// baseline (speedup 1.0000x reference)
#include <cuda_runtime.h>
#include <cuda_fp16.h>
#include <math.h>
#include <float.h>

#define BGR   32
#define NPER0 1024
#define N0    (BGR * NPER0)
#define HID   128
#define NE    524288
#define KK1   512
#define KK2   256
#define KK3   128
#define NC    10
#define MAXDEG 128
#define N1    (BGR * KK1)
#define N2    (BGR * KK2)

// ---------------- scratch (static device memory) ----------------
__device__ __align__(16) float  g_X[N0 * HID];
__device__ __align__(16) __half g_XS[N0 * HID];
__device__ float g_catd[N0];
__device__ int   g_cnt0[N0];     // zero at load; re-zeroed by k_mlp
__device__ int   g_cnt1[N1];
__device__ int   g_cnt2[N2];
__device__ int   g_csrA[N0 * MAXDEG];
__device__ int   g_csrB[N1 * MAXDEG];
__device__ __align__(16) float g_r[BGR * 2 * HID];

static inline int ceil_div(int a, int b) { return (a + b - 1) / b; }

__device__ __forceinline__ unsigned f2u_ord(float f) {
    unsigned u = __float_as_uint(f);
    return (u & 0x80000000u) ? ~u : (u | 0x80000000u);
}
__device__ __forceinline__ float u2f_ord(unsigned m) {
    unsigned u = (m & 0x80000000u) ? (m & 0x7FFFFFFFu) : ~m;
    return __uint_as_float(u);
}

__device__ __forceinline__ uint2 pack_h4(float a, float b, float c, float d) {
    union { uint2 u; __half2 h[2]; } pk;
    pk.h[0] = __floats2half2_rn(a, b);
    pk.h[1] = __floats2half2_rn(c, d);
    return pk.u;
}
__device__ __forceinline__ float4 unpack_h4(uint2 u) {
    union { uint2 u; __half2 h[2]; } pk;
    pk.u = u;
    float2 f0 = __half22float2(pk.h[0]);
    float2 f1 = __half22float2(pk.h[1]);
    return make_float4(f0.x, f0.y, f1.x, f1.y);
}

__device__ __forceinline__ unsigned long long shfl_xor_u64(unsigned long long v, int m) {
    unsigned lo = (unsigned)v, hi = (unsigned)(v >> 32);
    lo = __shfl_xor_sync(0xffffffffu, lo, m);
    hi = __shfl_xor_sync(0xffffffffu, hi, m);
    return ((unsigned long long)hi << 32) | lo;
}

// ---------------- kernels ----------------
__global__ void k_build(const int* __restrict__ src, const int* __restrict__ dst,
                        int* __restrict__ cnt, int* __restrict__ csr) {
    int e4 = blockIdx.x * blockDim.x + threadIdx.x;
    if (e4 >= NE / 4) return;
    int4 d4 = ((const int4*)dst)[e4];
    int4 s4 = ((const int4*)src)[e4];
    int t0 = atomicAdd(&cnt[d4.x], 1);
    int t1 = atomicAdd(&cnt[d4.y], 1);
    int t2 = atomicAdd(&cnt[d4.z], 1);
    int t3 = atomicAdd(&cnt[d4.w], 1);
    if (t0 < MAXDEG) csr[d4.x * MAXDEG + t0] = s4.x;
    if (t1 < MAXDEG) csr[d4.y * MAXDEG + t1] = s4.y;
    if (t2 < MAXDEG) csr[d4.z * MAXDEG + t2] = s4.z;
    if (t3 < MAXDEG) csr[d4.w * MAXDEG + t3] = s4.w;
}

__global__ void k_scale(const float* __restrict__ Xin, const int* __restrict__ cnt,
                        __half* __restrict__ Xs, int n) {
    int i = blockIdx.x * blockDim.x + threadIdx.x;
    if (i >= n * 32) return;
    float d = rsqrtf((float)(cnt[i >> 5] + 1));
    float4 v = ((const float4*)Xin)[i];
    ((uint2*)Xs)[i] = pack_h4(v.x * d, v.y * d, v.z * d, v.w * d);
}

// Warp-per-node fused agg(fp16) + per-head projection + relu + attention (frozen).
#define NPB3 32
__global__ void __launch_bounds__(256) k_aggXP(
        const __half* __restrict__ Xs, const int* __restrict__ cnt,
        const int* __restrict__ csr,
        const float* __restrict__ W, const float* __restrict__ b,
        const float* __restrict__ A, const float* __restrict__ psW,
        float* __restrict__ Xout, float* __restrict__ catd, int n) {
    __shared__ float sW[4096];
    int t = threadIdx.x;
    #pragma unroll
    for (int i = 0; i < 16; i++) sW[i * 256 + t] = W[i * 256 + t];
    __syncthreads();
    int w = t >> 5, lane = t & 31;
    int head = lane >> 3;
    int baseLane = head << 3;
    int oct = lane & 7;
    const uint2* Xh = (const uint2*)Xs;
    float4 b4  = ((const float4*)b)[lane];
    float4 A4  = ((const float4*)A)[lane];
    float4 pw4 = ((const float4*)psW)[lane];
    const float* whBase = sW + head * 1024 + oct * 4;
    int base = blockIdx.x * NPB3;
    #pragma unroll 1
    for (int it = 0; it < NPB3 / 8; it++) {
        int node = base + it * 8 + w;
        if (node >= n) break;
        int deg = cnt[node];
        float di = rsqrtf((float)(deg + 1));
        const int* row = csr + (size_t)node * MAXDEG;
        float4 acc = unpack_h4(Xh[(size_t)node * 32 + lane]);
        int j = 0;
        for (; j + 4 <= deg; j += 4) {
            int4 s4 = *(const int4*)(row + j);
            float4 v0 = unpack_h4(Xh[(size_t)s4.x * 32 + lane]);
            float4 v1 = unpack_h4(Xh[(size_t)s4.y * 32 + lane]);
            float4 v2 = unpack_h4(Xh[(size_t)s4.z * 32 + lane]);
            float4 v3 = unpack_h4(Xh[(size_t)s4.w * 32 + lane]);
            acc.x += (v0.x + v1.x) + (v2.x + v3.x);
            acc.y += (v0.y + v1.y) + (v2.y + v3.y);
            acc.z += (v0.z + v1.z) + (v2.z + v3.z);
            acc.w += (v0.w + v1.w) + (v2.w + v3.w);
        }
        for (; j < deg; j++) {
            float4 v0 = unpack_h4(Xh[(size_t)row[j] * 32 + lane]);
            acc.x += v0.x; acc.y += v0.y; acc.z += v0.z; acc.w += v0.w;
        }
        float4 v = make_float4(acc.x * di, acc.y * di, acc.z * di, acc.w * di);
        float4 o = make_float4(0.f, 0.f, 0.f, 0.f);
        #pragma unroll
        for (int i = 0; i < 8; i++) {
            int sl = baseLane + i;
            float vv0 = __shfl_sync(0xffffffffu, v.x, sl);
            float vv1 = __shfl_sync(0xffffffffu, v.y, sl);
            float vv2 = __shfl_sync(0xffffffffu, v.z, sl);
            float vv3 = __shfl_sync(0xffffffffu, v.w, sl);
            const float* wp = whBase + (i * 4) * 32;
            float4 w0 = *(const float4*)(wp);
            float4 w1 = *(const float4*)(wp + 32);
            float4 w2 = *(const float4*)(wp + 64);
            float4 w3 = *(const float4*)(wp + 96);
            o.x = fmaf(vv0, w0.x, o.x); o.y = fmaf(vv0, w0.y, o.y);
            o.z = fmaf(vv0, w0.z, o.z); o.w = fmaf(vv0, w0.w, o.w);
            o.x = fmaf(vv1, w1.x, o.x); o.y = fmaf(vv1, w1.y, o.y);
            o.z = fmaf(vv1, w1.z, o.z); o.w = fmaf(vv1, w1.w, o.w);
            o.x = fmaf(vv2, w2.x, o.x); o.y = fmaf(vv2, w2.y, o.y);
            o.z = fmaf(vv2, w2.z, o.z); o.w = fmaf(vv2, w2.w, o.w);
            o.x = fmaf(vv3, w3.x, o.x); o.y = fmaf(vv3, w3.y, o.y);
            o.z = fmaf(vv3, w3.z, o.z); o.w = fmaf(vv3, w3.w, o.w);
        }
        o.x = fmaxf(o.x + b4.x, 0.f);
        o.y = fmaxf(o.y + b4.y, 0.f);
        o.z = fmaxf(o.z + b4.z, 0.f);
        o.w = fmaxf(o.w + b4.w, 0.f);
        ((float4*)Xout)[(size_t)node * 32 + lane] = o;
        float att = o.x * A4.x + o.y * A4.y + o.z * A4.z + o.w * A4.w;
        att += __shfl_xor_sync(0xffffffffu, att, 1);
        att += __shfl_xor_sync(0xffffffffu, att, 2);
        att += __shfl_xor_sync(0xffffffffu, att, 4);
        float cp = att * (o.x * pw4.x + o.y * pw4.y + o.z * pw4.z + o.w * pw4.w);
        #pragma unroll
        for (int ofs = 16; ofs > 0; ofs >>= 1)
            cp += __shfl_xor_sync(0xffffffffu, cp, ofs);
        if (lane == 0) catd[node] = cp * di;
    }
}

// Per-graph select, 1024 threads: warp-parallel score gather + hybrid sort +
// warp-parallel ballot compaction + vectorized pool/readout.
__global__ void __launch_bounds__(1024) k_select(
        const float* __restrict__ catd,
        const int* __restrict__ cnt, const int* __restrict__ csrIn,
        const float* __restrict__ psb, const float* __restrict__ Xmid,
        __half* __restrict__ XSout, float* __restrict__ r,
        int nper, int k, int accum,
        int* __restrict__ csrOut, int* __restrict__ cntOut) {
    __shared__ unsigned long long skey[1024];
    __shared__ float scd[1024];
    __shared__ int   snmap[1024];
    __shared__ int   sdeg[512];
    __shared__ float4 sred[1024];
    int g = blockIdx.x, t = threadIdx.x;
    int lane = t & 31, c = t >> 5;          // warp id c, 32 warps
    int base = g * nper;
    if (t < nper) {
        scd[t] = catd[base + t];
        snmap[t] = -1;
    }
    __syncthreads();
    float pb = psb[0];
    // warp-parallel score gather: warp c handles nodes c, c+32, ...
    for (int i = c; i < nper; i += 32) {
        int node = base + i;
        int deg = cnt[node];
        const int* row = csrIn + (size_t)node * MAXDEG;
        float s2 = 0.f;
        for (int j = lane; j < deg; j += 32) s2 += scd[row[j] - base];
        #pragma unroll
        for (int ofs = 16; ofs > 0; ofs >>= 1)
            s2 += __shfl_xor_sync(0xffffffffu, s2, ofs);
        if (lane == 0) {
            float din = rsqrtf((float)(deg + 1));
            float sc = fmaf(s2 + scd[i] * din, din, pb);
            skey[i] = ((unsigned long long)f2u_ord(sc) << 32) | (unsigned)(~i);
        }
    }
    __syncthreads();
    // hybrid bitonic sort (descending)
    for (int ks = 2; ks <= nper; ks <<= 1) {
        for (int j = ks >> 1; j >= 32; j >>= 1) {
            int p = t;
            if (p < (nper >> 1)) {
                int i = ((p & ~(j - 1)) << 1) | (p & (j - 1));
                int ixj = i | j;
                unsigned long long ka = skey[i], kb = skey[ixj];
                bool dirUp = ((i & ks) == 0);
                if (dirUp ? (ka < kb) : (ka > kb)) { skey[i] = kb; skey[ixj] = ka; }
            }
            __syncthreads();
        }
        {
            unsigned long long key = (t < nper) ? skey[t] : 0ull;
            bool up = ((t & ks) == 0);
            int jstart = (ks >> 1 < 16) ? (ks >> 1) : 16;
            for (int j = jstart; j >= 1; j >>= 1) {
                unsigned long long other = shfl_xor_u64(key, j);
                bool takeMax = (up == ((t & j) == 0));
                if (takeMax ? (other > key) : (other < key)) key = other;
            }
            if (t < nper) skey[t] = key;
            __syncthreads();
        }
    }
    if (t < k) {
        unsigned long long key = skey[t];
        snmap[(int)(~(unsigned)key)] = g * k + t;
        scd[t] = tanhf(u2f_ord((unsigned)(key >> 32)));
    }
    __syncthreads();
    // warp-parallel CSR compaction with ballot-ordered writes
    if (csrOut) {
        for (int i = c; i < nper; i += 32) {
            int nm = snmap[i];              // warp-uniform (i is)
            if (nm < 0) continue;
            int node = base + i;
            int deg = cnt[node];
            const int* row = csrIn + (size_t)node * MAXDEG;
            int* orow = csrOut + (size_t)nm * MAXDEG;
            int cct = 0;
            for (int jb = 0; jb < deg; jb += 32) {
                int j = jb + lane;
                int m2 = (j < deg) ? snmap[row[j] - base] : -1;
                unsigned msk = __ballot_sync(0xffffffffu, m2 >= 0);
                if (m2 >= 0)
                    orow[cct + __popc(msk & ((1u << lane) - 1u))] = m2;
                cct += __popc(msk);
            }
            if (lane == 0) { cntOut[nm] = cct; sdeg[nm - g * k] = cct; }
        }
        __syncthreads();
    }
    // pool + readout (c = rank group, lane = float4 of features)
    const float4* Xmid4 = (const float4*)Xmid;
    float4 mx = make_float4(-FLT_MAX, -FLT_MAX, -FLT_MAX, -FLT_MAX);
    float4 sm = make_float4(0.f, 0.f, 0.f, 0.f);
    for (int j = c; j < k; j += 32) {
        int orig = base + (int)(~(unsigned)skey[j]);
        float tv = scd[j];
        float4 v = Xmid4[(size_t)orig * 32 + lane];
        v.x *= tv; v.y *= tv; v.z *= tv; v.w *= tv;
        if (XSout) {
            float dn = rsqrtf((float)(sdeg[j] + 1));
            ((uint2*)XSout)[(size_t)(g * k + j) * 32 + lane] =
                pack_h4(v.x * dn, v.y * dn, v.z * dn, v.w * dn);
        }
        mx.x = fmaxf(mx.x, v.x); mx.y = fmaxf(mx.y, v.y);
        mx.z = fmaxf(mx.z, v.z); mx.w = fmaxf(mx.w, v.w);
        sm.x += v.x; sm.y += v.y; sm.z += v.z; sm.w += v.w;
    }
    sred[c * 32 + lane] = mx;
    __syncthreads();
    for (int st = 16; st >= 1; st >>= 1) {
        if (c < st) {
            float4 a = sred[c * 32 + lane], bb = sred[(c + st) * 32 + lane];
            sred[c * 32 + lane] = make_float4(fmaxf(a.x, bb.x), fmaxf(a.y, bb.y),
                                              fmaxf(a.z, bb.z), fmaxf(a.w, bb.w));
        }
        __syncthreads();
    }
    if (t < 32) {
        float4 o = sred[lane];
        float4* rp = (float4*)(r + g * 256) + lane;
        if (accum) {
            float4 old = *rp;
            o.x += old.x; o.y += old.y; o.z += old.z; o.w += old.w;
        }
        *rp = o;
    }
    __syncthreads();
    sred[c * 32 + lane] = sm;
    __syncthreads();
    for (int st = 16; st >= 1; st >>= 1) {
        if (c < st) {
            float4 a = sred[c * 32 + lane], bb = sred[(c + st) * 32 + lane];
            sred[c * 32 + lane] = make_float4(a.x + bb.x, a.y + bb.y,
                                              a.z + bb.z, a.w + bb.w);
        }
        __syncthreads();
    }
    if (t < 32) {
        float4 o = sred[lane];
        float inv = 1.0f / (float)k;
        o.x *= inv; o.y *= inv; o.z *= inv; o.w *= inv;
        float4* rp = (float4*)(r + g * 256 + 128) + lane;
        if (accum) {
            float4 old = *rp;
            o.x += old.x; o.y += old.y; o.z += old.z; o.w += old.w;
        }
        *rp = o;
    }
}

__global__ void k_mlp(const float* __restrict__ r,
                      const float* __restrict__ l1W, const float* __restrict__ l1b,
                      const float* __restrict__ l2W, const float* __restrict__ l2b,
                      const float* __restrict__ l3W, const float* __restrict__ l3b,
                      float* __restrict__ out, int* __restrict__ cnt0z) {
    __shared__ float z0[256], z1[128], z2[64], z3[16];
    __shared__ float red2[2];
    int g = blockIdx.x, t = threadIdx.x;
    z0[t] = r[g * 256 + t];
    z0[t + 128] = r[g * 256 + 128 + t];
    __syncthreads();
    {
        float acc = l1b[t];
        for (int i = 0; i < 256; i++) acc = fmaf(z0[i], l1W[i * 128 + t], acc);
        z1[t] = fmaxf(acc, 0.f);
    }
    __syncthreads();
    if (t < 64) {
        float acc = l2b[t];
        for (int i = 0; i < 128; i++) acc = fmaf(z1[i], l2W[i * 64 + t], acc);
        z2[t] = fmaxf(acc, 0.f);
    }
    __syncthreads();
    if (t < NC) {
        float acc = l3b[t];
        for (int i = 0; i < 64; i++) acc = fmaf(z2[i], l3W[i * NC + t], acc);
        z3[t] = acc;
    }
    __syncthreads();
    if (t == 0) {
        float m = -FLT_MAX;
        for (int c = 0; c < NC; c++) m = fmaxf(m, z3[c]);
        float s = 0.f;
        for (int c = 0; c < NC; c++) s += expf(z3[c] - m);
        red2[0] = m; red2[1] = logf(s);
    }
    __syncthreads();
    if (t < NC) out[g * NC + t] = z3[t] - red2[0] - red2[1];
    for (int i = g * 128 + t; i < N0; i += BGR * 128) cnt0z[i] = 0;
}

// ---------------- host side ----------------
extern "C" void kernel_launch(void* const* d_in, const int* in_sizes, int n_in,
                              void* d_out, int out_size) {
    const float* x   = (const float*)d_in[0];
    const int*   src = (const int*)d_in[1];
    const int*   dst = (const int*)d_in[2];
    const float* W1 = (const float*)d_in[3];
    const float* b1 = (const float*)d_in[4];
    const float* A1 = (const float*)d_in[5];
    const float* ps1W = (const float*)d_in[6];
    const float* ps1b = (const float*)d_in[7];
    const float* W2 = (const float*)d_in[8];
    const float* b2 = (const float*)d_in[9];
    const float* A2 = (const float*)d_in[10];
    const float* ps2W = (const float*)d_in[11];
    const float* ps2b = (const float*)d_in[12];
    const float* W3 = (const float*)d_in[13];
    const float* b3 = (const float*)d_in[14];
    const float* A3 = (const float*)d_in[15];
    const float* ps3W = (const float*)d_in[16];
    const float* ps3b = (const float*)d_in[17];
    const float* l1W = (const float*)d_in[18];
    const float* l1b = (const float*)d_in[19];
    const float* l2W = (const float*)d_in[20];
    const float* l2b = (const float*)d_in[21];
    const float* l3W = (const float*)d_in[22];
    const float* l3b = (const float*)d_in[23];
    float* out = (float*)d_out;

    float *X, *catd, *r;
    __half *XS;
    int *cnt0, *cnt1, *cnt2, *csrA, *csrB;
    cudaGetSymbolAddress((void**)&X, g_X);
    cudaGetSymbolAddress((void**)&XS, g_XS);
    cudaGetSymbolAddress((void**)&catd, g_catd);
    cudaGetSymbolAddress((void**)&r, g_r);
    cudaGetSymbolAddress((void**)&cnt0, g_cnt0);
    cudaGetSymbolAddress((void**)&cnt1, g_cnt1);
    cudaGetSymbolAddress((void**)&cnt2, g_cnt2);
    cudaGetSymbolAddress((void**)&csrA, g_csrA);
    cudaGetSymbolAddress((void**)&csrB, g_csrB);

    k_build<<<ceil_div(NE / 4, 256), 256>>>(src, dst, cnt0, csrA);

    // stage 1
    k_scale<<<ceil_div(N0 * 32, 256), 256>>>(x, cnt0, XS, N0);
    k_aggXP<<<ceil_div(N0, NPB3), 256>>>(XS, cnt0, csrA,
                                         W1, b1, A1, ps1W, X, catd, N0);
    k_select<<<BGR, 1024>>>(catd, cnt0, csrA, ps1b, X,
                            XS, r, NPER0, KK1, 0, csrB, cnt1);
    // stage 2
    k_aggXP<<<ceil_div(N1, NPB3), 256>>>(XS, cnt1, csrB,
                                         W2, b2, A2, ps2W, X, catd, N1);
    k_select<<<BGR, 1024>>>(catd, cnt1, csrB, ps2b, X,
                            XS, r, KK1, KK2, 1, csrA, cnt2);
    // stage 3
    k_aggXP<<<ceil_div(N2, NPB3), 256>>>(XS, cnt2, csrA,
                                         W3, b3, A3, ps3W, X, catd, N2);
    k_select<<<BGR, 1024>>>(catd, cnt2, csrA, ps3b, X,
                            nullptr, r, KK2, KK3, 1, nullptr, nullptr);

    k_mlp<<<BGR, 128>>>(r, l1W, l1b, l2W, l2b, l3W, l3b, out, cnt0);
}

// round 15
// speedup vs baseline: 1.2813x; 1.2813x over previous
#include <cuda_runtime.h>
#include <cuda_fp16.h>
#include <math.h>
#include <float.h>

#define BGR   32
#define NPER0 1024
#define N0    (BGR * NPER0)
#define HID   128
#define NE    524288
#define KK1   512
#define KK2   256
#define KK3   128
#define NC    10
#define MAXDEG 128
#define N1    (BGR * KK1)
#define N2    (BGR * KK2)

// ---------------- scratch (static device memory) ----------------
__device__ __align__(16) float  g_X[N0 * HID];
__device__ __align__(16) __half g_XS[N0 * HID];
__device__ float g_catd[N0];
__device__ float g_score[N0];
__device__ int   g_cnt0[N0];     // zero at load; re-zeroed by k_mlp
__device__ int   g_cnt1[N1];
__device__ int   g_cnt2[N2];
__device__ int   g_csrA[N0 * MAXDEG];
__device__ int   g_csrB[N1 * MAXDEG];
__device__ __align__(16) float g_r[BGR * 2 * HID];

static inline int ceil_div(int a, int b) { return (a + b - 1) / b; }

__device__ __forceinline__ unsigned f2u_ord(float f) {
    unsigned u = __float_as_uint(f);
    return (u & 0x80000000u) ? ~u : (u | 0x80000000u);
}
__device__ __forceinline__ float u2f_ord(unsigned m) {
    unsigned u = (m & 0x80000000u) ? (m & 0x7FFFFFFFu) : ~m;
    return __uint_as_float(u);
}

__device__ __forceinline__ uint2 pack_h4(float a, float b, float c, float d) {
    union { uint2 u; __half2 h[2]; } pk;
    pk.h[0] = __floats2half2_rn(a, b);
    pk.h[1] = __floats2half2_rn(c, d);
    return pk.u;
}
__device__ __forceinline__ float4 unpack_h4(uint2 u) {
    union { uint2 u; __half2 h[2]; } pk;
    pk.u = u;
    float2 f0 = __half22float2(pk.h[0]);
    float2 f1 = __half22float2(pk.h[1]);
    return make_float4(f0.x, f0.y, f1.x, f1.y);
}

__device__ __forceinline__ unsigned long long shfl_xor_u64(unsigned long long v, int m) {
    unsigned lo = (unsigned)v, hi = (unsigned)(v >> 32);
    lo = __shfl_xor_sync(0xffffffffu, lo, m);
    hi = __shfl_xor_sync(0xffffffffu, hi, m);
    return ((unsigned long long)hi << 32) | lo;
}

// ---------------- kernels ----------------
__global__ void k_build(const int* __restrict__ src, const int* __restrict__ dst,
                        int* __restrict__ cnt, int* __restrict__ csr) {
    int e4 = blockIdx.x * blockDim.x + threadIdx.x;
    if (e4 >= NE / 4) return;
    int4 d4 = ((const int4*)dst)[e4];
    int4 s4 = ((const int4*)src)[e4];
    int t0 = atomicAdd(&cnt[d4.x], 1);
    int t1 = atomicAdd(&cnt[d4.y], 1);
    int t2 = atomicAdd(&cnt[d4.z], 1);
    int t3 = atomicAdd(&cnt[d4.w], 1);
    if (t0 < MAXDEG) csr[d4.x * MAXDEG + t0] = s4.x;
    if (t1 < MAXDEG) csr[d4.y * MAXDEG + t1] = s4.y;
    if (t2 < MAXDEG) csr[d4.z * MAXDEG + t2] = s4.z;
    if (t3 < MAXDEG) csr[d4.w * MAXDEG + t3] = s4.w;
}

__global__ void k_scale(const float* __restrict__ Xin, const int* __restrict__ cnt,
                        __half* __restrict__ Xs, int n) {
    int i = blockIdx.x * blockDim.x + threadIdx.x;
    if (i >= n * 32) return;
    float d = rsqrtf((float)(cnt[i >> 5] + 1));
    float4 v = ((const float4*)Xin)[i];
    ((uint2*)Xs)[i] = pack_h4(v.x * d, v.y * d, v.z * d, v.w * d);
}

// Warp-per-node fused agg(fp16) + per-head projection + relu + attention (frozen).
#define NPB3 32
__global__ void __launch_bounds__(256) k_aggXP(
        const __half* __restrict__ Xs, const int* __restrict__ cnt,
        const int* __restrict__ csr,
        const float* __restrict__ W, const float* __restrict__ b,
        const float* __restrict__ A, const float* __restrict__ psW,
        float* __restrict__ Xout, float* __restrict__ catd, int n) {
    __shared__ float sW[4096];
    int t = threadIdx.x;
    #pragma unroll
    for (int i = 0; i < 16; i++) sW[i * 256 + t] = W[i * 256 + t];
    __syncthreads();
    int w = t >> 5, lane = t & 31;
    int head = lane >> 3;
    int baseLane = head << 3;
    int oct = lane & 7;
    const uint2* Xh = (const uint2*)Xs;
    float4 b4  = ((const float4*)b)[lane];
    float4 A4  = ((const float4*)A)[lane];
    float4 pw4 = ((const float4*)psW)[lane];
    const float* whBase = sW + head * 1024 + oct * 4;
    int base = blockIdx.x * NPB3;
    #pragma unroll 1
    for (int it = 0; it < NPB3 / 8; it++) {
        int node = base + it * 8 + w;
        if (node >= n) break;
        int deg = cnt[node];
        float di = rsqrtf((float)(deg + 1));
        const int* row = csr + (size_t)node * MAXDEG;
        float4 acc = unpack_h4(Xh[(size_t)node * 32 + lane]);
        int j = 0;
        for (; j + 4 <= deg; j += 4) {
            int4 s4 = *(const int4*)(row + j);
            float4 v0 = unpack_h4(Xh[(size_t)s4.x * 32 + lane]);
            float4 v1 = unpack_h4(Xh[(size_t)s4.y * 32 + lane]);
            float4 v2 = unpack_h4(Xh[(size_t)s4.z * 32 + lane]);
            float4 v3 = unpack_h4(Xh[(size_t)s4.w * 32 + lane]);
            acc.x += (v0.x + v1.x) + (v2.x + v3.x);
            acc.y += (v0.y + v1.y) + (v2.y + v3.y);
            acc.z += (v0.z + v1.z) + (v2.z + v3.z);
            acc.w += (v0.w + v1.w) + (v2.w + v3.w);
        }
        for (; j < deg; j++) {
            float4 v0 = unpack_h4(Xh[(size_t)row[j] * 32 + lane]);
            acc.x += v0.x; acc.y += v0.y; acc.z += v0.z; acc.w += v0.w;
        }
        float4 v = make_float4(acc.x * di, acc.y * di, acc.z * di, acc.w * di);
        float4 o = make_float4(0.f, 0.f, 0.f, 0.f);
        #pragma unroll
        for (int i = 0; i < 8; i++) {
            int sl = baseLane + i;
            float vv0 = __shfl_sync(0xffffffffu, v.x, sl);
            float vv1 = __shfl_sync(0xffffffffu, v.y, sl);
            float vv2 = __shfl_sync(0xffffffffu, v.z, sl);
            float vv3 = __shfl_sync(0xffffffffu, v.w, sl);
            const float* wp = whBase + (i * 4) * 32;
            float4 w0 = *(const float4*)(wp);
            float4 w1 = *(const float4*)(wp + 32);
            float4 w2 = *(const float4*)(wp + 64);
            float4 w3 = *(const float4*)(wp + 96);
            o.x = fmaf(vv0, w0.x, o.x); o.y = fmaf(vv0, w0.y, o.y);
            o.z = fmaf(vv0, w0.z, o.z); o.w = fmaf(vv0, w0.w, o.w);
            o.x = fmaf(vv1, w1.x, o.x); o.y = fmaf(vv1, w1.y, o.y);
            o.z = fmaf(vv1, w1.z, o.z); o.w = fmaf(vv1, w1.w, o.w);
            o.x = fmaf(vv2, w2.x, o.x); o.y = fmaf(vv2, w2.y, o.y);
            o.z = fmaf(vv2, w2.z, o.z); o.w = fmaf(vv2, w2.w, o.w);
            o.x = fmaf(vv3, w3.x, o.x); o.y = fmaf(vv3, w3.y, o.y);
            o.z = fmaf(vv3, w3.z, o.z); o.w = fmaf(vv3, w3.w, o.w);
        }
        o.x = fmaxf(o.x + b4.x, 0.f);
        o.y = fmaxf(o.y + b4.y, 0.f);
        o.z = fmaxf(o.z + b4.z, 0.f);
        o.w = fmaxf(o.w + b4.w, 0.f);
        ((float4*)Xout)[(size_t)node * 32 + lane] = o;
        float att = o.x * A4.x + o.y * A4.y + o.z * A4.z + o.w * A4.w;
        att += __shfl_xor_sync(0xffffffffu, att, 1);
        att += __shfl_xor_sync(0xffffffffu, att, 2);
        att += __shfl_xor_sync(0xffffffffu, att, 4);
        float cp = att * (o.x * pw4.x + o.y * pw4.y + o.z * pw4.z + o.w * pw4.w);
        #pragma unroll
        for (int ofs = 16; ofs > 0; ofs >>= 1)
            cp += __shfl_xor_sync(0xffffffffu, cp, ofs);
        if (lane == 0) catd[node] = cp * di;
    }
}

// Full-chip score gather (thread-per-node, node-parallel, uses all SMs):
// score = (sum_nbr catd + catd_self * dinv) * dinv + psb
__global__ void k_score(const float* __restrict__ catd, const int* __restrict__ cnt,
                        const int* __restrict__ csr, const float* __restrict__ psb,
                        float* __restrict__ score, int n) {
    int i = blockIdx.x * blockDim.x + threadIdx.x;
    if (i >= n) return;
    int deg = cnt[i];
    const int* row = csr + (size_t)i * MAXDEG;
    float s2 = 0.f;
    for (int j = 0; j < deg; j++) s2 += catd[row[j]];
    float din = rsqrtf((float)(deg + 1));
    score[i] = fmaf(s2 + catd[i] * din, din, psb[0]);
}

// Per-graph select, 1024 threads (R13 structure, gather removed):
// load scores + hybrid bitonic sort + thread-per-row compaction + pool/readout.
__global__ void __launch_bounds__(1024) k_select(
        const float* __restrict__ score,
        const int* __restrict__ cnt, const int* __restrict__ csrIn,
        const float* __restrict__ Xmid,
        __half* __restrict__ XSout, float* __restrict__ r,
        int nper, int k, int accum,
        int* __restrict__ csrOut, int* __restrict__ cntOut) {
    __shared__ unsigned long long skey[1024];
    __shared__ float scd[1024];          // tanh of rank-j score (post-sort)
    __shared__ int   snmap[1024];
    __shared__ int   sdeg[512];
    __shared__ float4 sred[1024];
    int g = blockIdx.x, t = threadIdx.x;
    int base = g * nper;
    if (t < nper) {
        snmap[t] = -1;
        skey[t] = ((unsigned long long)f2u_ord(score[base + t]) << 32) | (unsigned)(~t);
    }
    __syncthreads();
    // hybrid bitonic sort (descending): smem pair-steps j>=32, shuffle j<=16
    for (int ks = 2; ks <= nper; ks <<= 1) {
        for (int j = ks >> 1; j >= 32; j >>= 1) {
            int p = t;
            if (p < (nper >> 1)) {
                int i = ((p & ~(j - 1)) << 1) | (p & (j - 1));
                int ixj = i | j;
                unsigned long long ka = skey[i], kb = skey[ixj];
                bool dirUp = ((i & ks) == 0);
                if (dirUp ? (ka < kb) : (ka > kb)) { skey[i] = kb; skey[ixj] = ka; }
            }
            __syncthreads();
        }
        {
            unsigned long long key = (t < nper) ? skey[t] : 0ull;
            bool up = ((t & ks) == 0);
            int jstart = (ks >> 1 < 16) ? (ks >> 1) : 16;
            for (int j = jstart; j >= 1; j >>= 1) {
                unsigned long long other = shfl_xor_u64(key, j);
                bool takeMax = (up == ((t & j) == 0));
                if (takeMax ? (other > key) : (other < key)) key = other;
            }
            if (t < nper) skey[t] = key;
            __syncthreads();
        }
    }
    if (t < k) {
        unsigned long long key = skey[t];
        snmap[(int)(~(unsigned)key)] = g * k + t;
        scd[t] = tanhf(u2f_ord((unsigned)(key >> 32)));
    }
    __syncthreads();
    // CSR -> CSR compaction (thread-per-row, local cursor)
    if (csrOut) {
        if (t < nper) {
            int nm = snmap[t];
            if (nm >= 0) {
                int node = base + t;
                int deg = cnt[node];
                const int* row = csrIn + (size_t)node * MAXDEG;
                int* orow = csrOut + (size_t)nm * MAXDEG;
                int cct = 0;
                for (int j = 0; j < deg; j++) {
                    int m2 = snmap[row[j] - base];
                    if (m2 >= 0) orow[cct++] = m2;
                }
                cntOut[nm] = cct;
                sdeg[nm - g * k] = cct;
            }
        }
        __syncthreads();
    }
    // pool + readout (c = rank group, f4 = float4 lane of features)
    int f4 = t & 31, c = t >> 5;
    const float4* Xmid4 = (const float4*)Xmid;
    float4 mx = make_float4(-FLT_MAX, -FLT_MAX, -FLT_MAX, -FLT_MAX);
    float4 sm = make_float4(0.f, 0.f, 0.f, 0.f);
    for (int j = c; j < k; j += 32) {
        int orig = base + (int)(~(unsigned)skey[j]);
        float tv = scd[j];
        float4 v = Xmid4[(size_t)orig * 32 + f4];
        v.x *= tv; v.y *= tv; v.z *= tv; v.w *= tv;
        if (XSout) {
            float dn = rsqrtf((float)(sdeg[j] + 1));
            ((uint2*)XSout)[(size_t)(g * k + j) * 32 + f4] =
                pack_h4(v.x * dn, v.y * dn, v.z * dn, v.w * dn);
        }
        mx.x = fmaxf(mx.x, v.x); mx.y = fmaxf(mx.y, v.y);
        mx.z = fmaxf(mx.z, v.z); mx.w = fmaxf(mx.w, v.w);
        sm.x += v.x; sm.y += v.y; sm.z += v.z; sm.w += v.w;
    }
    sred[c * 32 + f4] = mx;
    __syncthreads();
    for (int st = 16; st >= 1; st >>= 1) {
        if (c < st) {
            float4 a = sred[c * 32 + f4], bb = sred[(c + st) * 32 + f4];
            sred[c * 32 + f4] = make_float4(fmaxf(a.x, bb.x), fmaxf(a.y, bb.y),
                                            fmaxf(a.z, bb.z), fmaxf(a.w, bb.w));
        }
        __syncthreads();
    }
    if (t < 32) {
        float4 o = sred[f4];
        float4* rp = (float4*)(r + g * 256) + f4;
        if (accum) {
            float4 old = *rp;
            o.x += old.x; o.y += old.y; o.z += old.z; o.w += old.w;
        }
        *rp = o;
    }
    __syncthreads();
    sred[c * 32 + f4] = sm;
    __syncthreads();
    for (int st = 16; st >= 1; st >>= 1) {
        if (c < st) {
            float4 a = sred[c * 32 + f4], bb = sred[(c + st) * 32 + f4];
            sred[c * 32 + f4] = make_float4(a.x + bb.x, a.y + bb.y,
                                            a.z + bb.z, a.w + bb.w);
        }
        __syncthreads();
    }
    if (t < 32) {
        float4 o = sred[f4];
        float inv = 1.0f / (float)k;
        o.x *= inv; o.y *= inv; o.z *= inv; o.w *= inv;
        float4* rp = (float4*)(r + g * 256 + 128) + f4;
        if (accum) {
            float4 old = *rp;
            o.x += old.x; o.y += old.y; o.z += old.z; o.w += old.w;
        }
        *rp = o;
    }
}

__global__ void k_mlp(const float* __restrict__ r,
                      const float* __restrict__ l1W, const float* __restrict__ l1b,
                      const float* __restrict__ l2W, const float* __restrict__ l2b,
                      const float* __restrict__ l3W, const float* __restrict__ l3b,
                      float* __restrict__ out, int* __restrict__ cnt0z) {
    __shared__ float z0[256], z1[128], z2[64], z3[16];
    __shared__ float red2[2];
    int g = blockIdx.x, t = threadIdx.x;
    z0[t] = r[g * 256 + t];
    z0[t + 128] = r[g * 256 + 128 + t];
    __syncthreads();
    {
        float acc = l1b[t];
        for (int i = 0; i < 256; i++) acc = fmaf(z0[i], l1W[i * 128 + t], acc);
        z1[t] = fmaxf(acc, 0.f);
    }
    __syncthreads();
    if (t < 64) {
        float acc = l2b[t];
        for (int i = 0; i < 128; i++) acc = fmaf(z1[i], l2W[i * 64 + t], acc);
        z2[t] = fmaxf(acc, 0.f);
    }
    __syncthreads();
    if (t < NC) {
        float acc = l3b[t];
        for (int i = 0; i < 64; i++) acc = fmaf(z2[i], l3W[i * NC + t], acc);
        z3[t] = acc;
    }
    __syncthreads();
    if (t == 0) {
        float m = -FLT_MAX;
        for (int c = 0; c < NC; c++) m = fmaxf(m, z3[c]);
        float s = 0.f;
        for (int c = 0; c < NC; c++) s += expf(z3[c] - m);
        red2[0] = m; red2[1] = logf(s);
    }
    __syncthreads();
    if (t < NC) out[g * NC + t] = z3[t] - red2[0] - red2[1];
    for (int i = g * 128 + t; i < N0; i += BGR * 128) cnt0z[i] = 0;
}

// ---------------- host side ----------------
extern "C" void kernel_launch(void* const* d_in, const int* in_sizes, int n_in,
                              void* d_out, int out_size) {
    const float* x   = (const float*)d_in[0];
    const int*   src = (const int*)d_in[1];
    const int*   dst = (const int*)d_in[2];
    const float* W1 = (const float*)d_in[3];
    const float* b1 = (const float*)d_in[4];
    const float* A1 = (const float*)d_in[5];
    const float* ps1W = (const float*)d_in[6];
    const float* ps1b = (const float*)d_in[7];
    const float* W2 = (const float*)d_in[8];
    const float* b2 = (const float*)d_in[9];
    const float* A2 = (const float*)d_in[10];
    const float* ps2W = (const float*)d_in[11];
    const float* ps2b = (const float*)d_in[12];
    const float* W3 = (const float*)d_in[13];
    const float* b3 = (const float*)d_in[14];
    const float* A3 = (const float*)d_in[15];
    const float* ps3W = (const float*)d_in[16];
    const float* ps3b = (const float*)d_in[17];
    const float* l1W = (const float*)d_in[18];
    const float* l1b = (const float*)d_in[19];
    const float* l2W = (const float*)d_in[20];
    const float* l2b = (const float*)d_in[21];
    const float* l3W = (const float*)d_in[22];
    const float* l3b = (const float*)d_in[23];
    float* out = (float*)d_out;

    float *X, *catd, *score, *r;
    __half *XS;
    int *cnt0, *cnt1, *cnt2, *csrA, *csrB;
    cudaGetSymbolAddress((void**)&X, g_X);
    cudaGetSymbolAddress((void**)&XS, g_XS);
    cudaGetSymbolAddress((void**)&catd, g_catd);
    cudaGetSymbolAddress((void**)&score, g_score);
    cudaGetSymbolAddress((void**)&r, g_r);
    cudaGetSymbolAddress((void**)&cnt0, g_cnt0);
    cudaGetSymbolAddress((void**)&cnt1, g_cnt1);
    cudaGetSymbolAddress((void**)&cnt2, g_cnt2);
    cudaGetSymbolAddress((void**)&csrA, g_csrA);
    cudaGetSymbolAddress((void**)&csrB, g_csrB);

    k_build<<<ceil_div(NE / 4, 256), 256>>>(src, dst, cnt0, csrA);

    // stage 1
    k_scale<<<ceil_div(N0 * 32, 256), 256>>>(x, cnt0, XS, N0);
    k_aggXP<<<ceil_div(N0, NPB3), 256>>>(XS, cnt0, csrA,
                                         W1, b1, A1, ps1W, X, catd, N0);
    k_score<<<ceil_div(N0, 256), 256>>>(catd, cnt0, csrA, ps1b, score, N0);
    k_select<<<BGR, 1024>>>(score, cnt0, csrA, X,
                            XS, r, NPER0, KK1, 0, csrB, cnt1);
    // stage 2
    k_aggXP<<<ceil_div(N1, NPB3), 256>>>(XS, cnt1, csrB,
                                         W2, b2, A2, ps2W, X, catd, N1);
    k_score<<<ceil_div(N1, 256), 256>>>(catd, cnt1, csrB, ps2b, score, N1);
    k_select<<<BGR, 1024>>>(score, cnt1, csrB, X,
                            XS, r, KK1, KK2, 1, csrA, cnt2);
    // stage 3
    k_aggXP<<<ceil_div(N2, NPB3), 256>>>(XS, cnt2, csrA,
                                         W3, b3, A3, ps3W, X, catd, N2);
    k_score<<<ceil_div(N2, 256), 256>>>(catd, cnt2, csrA, ps3b, score, N2);
    k_select<<<BGR, 1024>>>(score, cnt2, csrA, X,
                            nullptr, r, KK2, KK3, 1, nullptr, nullptr);

    k_mlp<<<BGR, 128>>>(r, l1W, l1b, l2W, l2b, l3W, l3b, out, cnt0);
}